// round 8
// baseline (speedup 1.0000x reference)
#include <cuda_runtime.h>
#include <math.h>

#define N_NODES 50000
#define E_EDGES 500000
#define HDIM    128

// GEMM tile config
#define BM 64
#define BN 128
#define BK 32
#define TM 4
#define TN 8

typedef unsigned long long ull;

// packed fp32 helpers (FFMA2 path; bitwise-exact fp32)
#define FMA2(acc, a, b)  asm("fma.rn.f32x2 %0, %1, %2, %0;" : "+l"(acc) : "l"(a), "l"(b))
#define DUP2(d, s)       asm("mov.b64 %0, {%1, %1};" : "=l"(d) : "f"(s))
#define UNPK2(lo, hi, d) asm("mov.b64 {%0, %1}, %2;" : "=f"(lo), "=f"(hi) : "l"(d))

// ---- scratch (device globals; no allocation in kernel_launch) ----
__device__ int   g_deg[N_NODES];
__device__ int   g_rowstart[N_NODES + 1];
__device__ int   g_cursor[N_NODES];
__device__ int   g_csr_src[E_EDGES];
__device__ float g_aggn[(size_t)N_NODES * HDIM];
__device__ float g_h1  [(size_t)N_NODES * HDIM];
__device__ float g_U   [(size_t)N_NODES * 256];   // [Ua | Ub] per node

// ---------------- CSR build ----------------
__global__ void count_deg_kernel(const int* __restrict__ dst, int E) {
    int i = blockIdx.x * blockDim.x + threadIdx.x;
    if (i < E) atomicAdd(&g_deg[dst[i]], 1);
}

__global__ void scan_deg_kernel(int E) {
    __shared__ int ssum[1024];
    int tid = threadIdx.x;
    const int chunk = (N_NODES + 1023) / 1024;  // 49
    int start = tid * chunk;
    int end = min(start + chunk, N_NODES);
    int s = 0;
    for (int i = start; i < end; i++) s += g_deg[i];
    ssum[tid] = s;
    __syncthreads();
    for (int d = 1; d < 1024; d <<= 1) {
        int v = (tid >= d) ? ssum[tid - d] : 0;
        __syncthreads();
        ssum[tid] += v;
        __syncthreads();
    }
    int run = ssum[tid] - s;
    for (int i = start; i < end; i++) {
        g_rowstart[i] = run;
        g_cursor[i]   = run;
        run += g_deg[i];
    }
    if (tid == 1023) g_rowstart[N_NODES] = E;
}

__global__ void fill_csr_kernel(const int* __restrict__ src,
                                const int* __restrict__ dst, int E) {
    int i = blockIdx.x * blockDim.x + threadIdx.x;
    if (i < E) {
        int p = atomicAdd(&g_cursor[dst[i]], 1);
        g_csr_src[p] = src[i];
    }
}

// ---------------- mean aggregation: warp per node, MLP=8 ----------------
__global__ void agg_mean_kernel(const float* __restrict__ xin, int use_h1) {
    int gw   = (blockIdx.x * blockDim.x + threadIdx.x) >> 5;
    int lane = threadIdx.x & 31;
    if (gw >= N_NODES) return;
    const float* in = use_h1 ? g_h1 : xin;
    int s = g_rowstart[gw];
    int e = g_rowstart[gw + 1];
    float4 a0 = make_float4(0.f, 0.f, 0.f, 0.f);
    float4 a1 = make_float4(0.f, 0.f, 0.f, 0.f);
    float4 a2 = make_float4(0.f, 0.f, 0.f, 0.f);
    float4 a3 = make_float4(0.f, 0.f, 0.f, 0.f);
    int j = s;
    for (; j + 8 <= e; j += 8) {
        int s0 = g_csr_src[j],     s1 = g_csr_src[j + 1];
        int s2 = g_csr_src[j + 2], s3 = g_csr_src[j + 3];
        int s4 = g_csr_src[j + 4], s5 = g_csr_src[j + 5];
        int s6 = g_csr_src[j + 6], s7 = g_csr_src[j + 7];
        float4 v0 = *((const float4*)(in + (size_t)s0 * HDIM) + lane);
        float4 v1 = *((const float4*)(in + (size_t)s1 * HDIM) + lane);
        float4 v2 = *((const float4*)(in + (size_t)s2 * HDIM) + lane);
        float4 v3 = *((const float4*)(in + (size_t)s3 * HDIM) + lane);
        float4 v4 = *((const float4*)(in + (size_t)s4 * HDIM) + lane);
        float4 v5 = *((const float4*)(in + (size_t)s5 * HDIM) + lane);
        float4 v6 = *((const float4*)(in + (size_t)s6 * HDIM) + lane);
        float4 v7 = *((const float4*)(in + (size_t)s7 * HDIM) + lane);
        a0.x += v0.x; a0.y += v0.y; a0.z += v0.z; a0.w += v0.w;
        a1.x += v1.x; a1.y += v1.y; a1.z += v1.z; a1.w += v1.w;
        a2.x += v2.x; a2.y += v2.y; a2.z += v2.z; a2.w += v2.w;
        a3.x += v3.x; a3.y += v3.y; a3.z += v3.z; a3.w += v3.w;
        a0.x += v4.x; a0.y += v4.y; a0.z += v4.z; a0.w += v4.w;
        a1.x += v5.x; a1.y += v5.y; a1.z += v5.z; a1.w += v5.w;
        a2.x += v6.x; a2.y += v6.y; a2.z += v6.z; a2.w += v6.w;
        a3.x += v7.x; a3.y += v7.y; a3.z += v7.z; a3.w += v7.w;
    }
    for (; j + 2 <= e; j += 2) {
        int s0 = g_csr_src[j], s1 = g_csr_src[j + 1];
        float4 v0 = *((const float4*)(in + (size_t)s0 * HDIM) + lane);
        float4 v1 = *((const float4*)(in + (size_t)s1 * HDIM) + lane);
        a0.x += v0.x; a0.y += v0.y; a0.z += v0.z; a0.w += v0.w;
        a1.x += v1.x; a1.y += v1.y; a1.z += v1.z; a1.w += v1.w;
    }
    if (j < e) {
        int s0 = g_csr_src[j];
        float4 v0 = *((const float4*)(in + (size_t)s0 * HDIM) + lane);
        a0.x += v0.x; a0.y += v0.y; a0.z += v0.z; a0.w += v0.w;
    }
    float4 acc;
    acc.x = (a0.x + a1.x) + (a2.x + a3.x);
    acc.y = (a0.y + a1.y) + (a2.y + a3.y);
    acc.z = (a0.z + a1.z) + (a2.z + a3.z);
    acc.w = (a0.w + a1.w) + (a2.w + a3.w);
    float inv = 1.0f / (float)max(e - s, 1);
    acc.x *= inv; acc.y *= inv; acc.z *= inv; acc.w *= inv;
    *((float4*)(g_aggn + (size_t)gw * HDIM) + lane) = acc;
}

// ---------------- dup-A inner MMA: pure LDS + FFMA2 ----------------
// Asd: base of dup-packed A, row stride LDA ull elements. Ws: k-major weights.
template<int LDA>
__device__ __forceinline__ void mma_dup(const ull* __restrict__ Asd,
                                        const float Ws[BK][BN + 4],
                                        int tr, int tc, int koff,
                                        ull acc[TM][TN / 2]) {
#pragma unroll
    for (int k0 = 0; k0 < BK; k0 += 4) {
        ulonglong2 ad[TM][2];
#pragma unroll
        for (int r = 0; r < TM; r++) {
            const ull* ap = Asd + (size_t)(tr * TM + r) * LDA + koff + k0;
            ad[r][0] = *(const ulonglong2*)ap;
            ad[r][1] = *(const ulonglong2*)(ap + 2);
        }
#pragma unroll
        for (int jj = 0; jj < 4; jj++) {
            ulonglong2 b01 = *(const ulonglong2*)&Ws[k0 + jj][tc * TN];
            ulonglong2 b23 = *(const ulonglong2*)&Ws[k0 + jj][tc * TN + 4];
#pragma unroll
            for (int r = 0; r < TM; r++) {
                ull a2 = (jj == 0) ? ad[r][0].x : (jj == 1) ? ad[r][0].y
                       : (jj == 2) ? ad[r][1].x : ad[r][1].y;
                FMA2(acc[r][0], a2, b01.x);
                FMA2(acc[r][1], a2, b01.y);
                FMA2(acc[r][2], a2, b23.x);
                FMA2(acc[r][3], a2, b23.y);
            }
        }
    }
}

// stage A tile as dup-packed pairs + W tile transposed to k-major
__device__ __forceinline__ void stage_A_dup(ull Asd[BM][BK], int t, const float4 pa[2]) {
#pragma unroll
    for (int it = 0; it < 2; it++) {
        int j = t + it * 256;
        float4 v = pa[it];
        ull d0, d1, d2, d3;
        DUP2(d0, v.x); DUP2(d1, v.y); DUP2(d2, v.z); DUP2(d3, v.w);
        ulonglong2* dst = (ulonglong2*)&Asd[j >> 3][(j & 7) * 4];
        dst[0] = make_ulonglong2(d0, d1);
        dst[1] = make_ulonglong2(d2, d3);
    }
}

__device__ __forceinline__ void stage_W(float Ws[BK][BN + 4], int t, const float4 pw[4]) {
#pragma unroll
    for (int it = 0; it < 4; it++) {
        int j  = t + it * 256;
        int n  = j >> 3;
        int kq = j & 7;
        Ws[kq * 4 + 0][n] = pw[it].x;
        Ws[kq * 4 + 1][n] = pw[it].y;
        Ws[kq * 4 + 2][n] = pw[it].z;
        Ws[kq * 4 + 3][n] = pw[it].w;
    }
}

// ---------------- layer-1 GEMM: h1 = relu([agg|x] @ [Wl|Wr]^T + b) ----------------
__global__ __launch_bounds__(256, 3)
void layer_gemm_kernel(const float* __restrict__ Asec,
                       const float* __restrict__ Wl, const float* __restrict__ Wr,
                       const float* __restrict__ bias, float* __restrict__ out, int M) {
    __shared__ ull   Asd[BM][BK];
    __shared__ float Ws[BK][BN + 4];
    int t  = threadIdx.x;
    int tc = t & 15;
    int tr = t >> 4;
    int m0 = blockIdx.x * BM;
    ull acc[TM][TN / 2];
#pragma unroll
    for (int r = 0; r < TM; r++)
#pragma unroll
        for (int c = 0; c < TN / 2; c++) acc[r][c] = 0ULL;

    int arow = t >> 3, akq = t & 7;
    int gra0 = min(m0 + arow,      M - 1);
    int gra1 = min(m0 + arow + 32, M - 1);

    for (int kc = 0; kc < 8; kc++) {
        const float* Achunk = (kc < 4) ? g_aggn : Asec;
        const float* Wsrc   = (kc < 4) ? Wl : Wr;
        int kbase = (kc & 3) * BK;
        float4 pa[2], pw[4];
        pa[0] = *(const float4*)(Achunk + (size_t)gra0 * HDIM + kbase + akq * 4);
        pa[1] = *(const float4*)(Achunk + (size_t)gra1 * HDIM + kbase + akq * 4);
#pragma unroll
        for (int it = 0; it < 4; it++) {
            int j = t + it * 256;
            pw[it] = *(const float4*)(Wsrc + (size_t)(j >> 3) * HDIM + kbase + (j & 7) * 4);
        }
        stage_A_dup(Asd, t, pa);
        stage_W(Ws, t, pw);
        __syncthreads();
        mma_dup<BK>(&Asd[0][0], Ws, tr, tc, 0, acc);
        __syncthreads();
    }
    float4 b0 = *(const float4*)(bias + tc * TN);
    float4 b1 = *(const float4*)(bias + tc * TN + 4);
#pragma unroll
    for (int r = 0; r < TM; r++) {
        int gr = m0 + tr * TM + r;
        if (gr < M) {
            float v0, v1, v2, v3, v4, v5, v6, v7;
            UNPK2(v0, v1, acc[r][0]);
            UNPK2(v2, v3, acc[r][1]);
            UNPK2(v4, v5, acc[r][2]);
            UNPK2(v6, v7, acc[r][3]);
            float4 o0, o1;
            o0.x = fmaxf(v0 + b0.x, 0.f); o0.y = fmaxf(v1 + b0.y, 0.f);
            o0.z = fmaxf(v2 + b0.z, 0.f); o0.w = fmaxf(v3 + b0.w, 0.f);
            o1.x = fmaxf(v4 + b1.x, 0.f); o1.y = fmaxf(v5 + b1.y, 0.f);
            o1.z = fmaxf(v6 + b1.z, 0.f); o1.w = fmaxf(v7 + b1.w, 0.f);
            *(float4*)(out + (size_t)gr * HDIM + tc * TN)     = o0;
            *(float4*)(out + (size_t)gr * HDIM + tc * TN + 4) = o1;
        }
    }
}

// ---------------- fused layer-2 + U: h2 stays in smem, U = h2 @ [W3l;W3r]^T ----------------
// dynamic smem: Asd (16384 B) | Ws (16896 B) | H2d 64x128 ull (65536 B) = 98816 B
#define L2U_SMEM (16384 + 16896 + 65536)
extern __shared__ char smx[];

__global__ __launch_bounds__(256, 2)
void layer2u_kernel(const float* __restrict__ Wl2, const float* __restrict__ Wr2,
                    const float* __restrict__ b2, const float* __restrict__ W3, int M) {
    ull   (*Asd)[BK]      = (ull(*)[BK])smx;
    float (*Ws)[BN + 4]   = (float(*)[BN + 4])(smx + 16384);
    ull*   H2d            = (ull*)(smx + 16384 + 16896);   // [64][128] dup-packed h2
    int t  = threadIdx.x;
    int tc = t & 15;
    int tr = t >> 4;
    int m0 = blockIdx.x * BM;
    ull acc[TM][TN / 2];
#pragma unroll
    for (int r = 0; r < TM; r++)
#pragma unroll
        for (int c = 0; c < TN / 2; c++) acc[r][c] = 0ULL;

    int arow = t >> 3, akq = t & 7;
    int gra0 = min(m0 + arow,      M - 1);
    int gra1 = min(m0 + arow + 32, M - 1);

    // ---- phase A: h2 tile = relu([agg|h1] @ [Wl2|Wr2]^T + b2) ----
    for (int kc = 0; kc < 8; kc++) {
        const float* Achunk = (kc < 4) ? g_aggn : g_h1;
        const float* Wsrc   = (kc < 4) ? Wl2 : Wr2;
        int kbase = (kc & 3) * BK;
        float4 pa[2], pw[4];
        pa[0] = *(const float4*)(Achunk + (size_t)gra0 * HDIM + kbase + akq * 4);
        pa[1] = *(const float4*)(Achunk + (size_t)gra1 * HDIM + kbase + akq * 4);
#pragma unroll
        for (int it = 0; it < 4; it++) {
            int j = t + it * 256;
            pw[it] = *(const float4*)(Wsrc + (size_t)(j >> 3) * HDIM + kbase + (j & 7) * 4);
        }
        stage_A_dup(Asd, t, pa);
        stage_W(Ws, t, pw);
        __syncthreads();
        mma_dup<BK>(&Asd[0][0], Ws, tr, tc, 0, acc);
        __syncthreads();
    }
    // epilogue A: bias + relu, store dup-packed h2 into smem
    {
        float4 b0 = *(const float4*)(b2 + tc * TN);
        float4 b1 = *(const float4*)(b2 + tc * TN + 4);
#pragma unroll
        for (int r = 0; r < TM; r++) {
            int row = tr * TM + r;
            float v0, v1, v2, v3, v4, v5, v6, v7;
            UNPK2(v0, v1, acc[r][0]);
            UNPK2(v2, v3, acc[r][1]);
            UNPK2(v4, v5, acc[r][2]);
            UNPK2(v6, v7, acc[r][3]);
            v0 = fmaxf(v0 + b0.x, 0.f); v1 = fmaxf(v1 + b0.y, 0.f);
            v2 = fmaxf(v2 + b0.z, 0.f); v3 = fmaxf(v3 + b0.w, 0.f);
            v4 = fmaxf(v4 + b1.x, 0.f); v5 = fmaxf(v5 + b1.y, 0.f);
            v6 = fmaxf(v6 + b1.z, 0.f); v7 = fmaxf(v7 + b1.w, 0.f);
            ull d0, d1, d2, d3, d4, d5, d6, d7;
            DUP2(d0, v0); DUP2(d1, v1); DUP2(d2, v2); DUP2(d3, v3);
            DUP2(d4, v4); DUP2(d5, v5); DUP2(d6, v6); DUP2(d7, v7);
            ulonglong2* dst = (ulonglong2*)(H2d + (size_t)row * HDIM + tc * TN);
            dst[0] = make_ulonglong2(d0, d1);
            dst[1] = make_ulonglong2(d2, d3);
            dst[2] = make_ulonglong2(d4, d5);
            dst[3] = make_ulonglong2(d6, d7);
        }
    }
    // ---- phase B: U[:, y*128..] = h2tile @ W3half^T ----
    for (int y = 0; y < 2; y++) {
        const float* Wbase = W3 + y * 128;
#pragma unroll
        for (int r = 0; r < TM; r++)
#pragma unroll
            for (int c = 0; c < TN / 2; c++) acc[r][c] = 0ULL;
        for (int kc = 0; kc < 4; kc++) {
            int kbase = kc * BK;
            float4 pw[4];
#pragma unroll
            for (int it = 0; it < 4; it++) {
                int j = t + it * 256;
                pw[it] = *(const float4*)(Wbase + (size_t)(j >> 3) * 256 + kbase + (j & 7) * 4);
            }
            stage_W(Ws, t, pw);
            __syncthreads();
            mma_dup<HDIM>(H2d, Ws, tr, tc, kbase, acc);
            __syncthreads();
        }
#pragma unroll
        for (int r = 0; r < TM; r++) {
            int gr = m0 + tr * TM + r;
            if (gr < M) {
                float v0, v1, v2, v3, v4, v5, v6, v7;
                UNPK2(v0, v1, acc[r][0]);
                UNPK2(v2, v3, acc[r][1]);
                UNPK2(v4, v5, acc[r][2]);
                UNPK2(v6, v7, acc[r][3]);
                float* op = g_U + (size_t)gr * 256 + y * 128 + tc * TN;
                *(float4*)op       = make_float4(v0, v1, v2, v3);
                *(float4*)(op + 4) = make_float4(v4, v5, v6, v7);
            }
        }
    }
}

// ---------------- pair head: sigmoid(W4 . relu(Ua[a]+Ub[b]+b3) + b4) ----------------
__global__ __launch_bounds__(256)
void pair_kernel(const int* __restrict__ pairs,
                 const float* __restrict__ b3, const float* __restrict__ W4,
                 const float* __restrict__ b4, float* __restrict__ out, int P) {
    int w    = (blockIdx.x * blockDim.x + threadIdx.x) >> 5;
    int lane = threadIdx.x & 31;
    if (w >= P) return;
    int na = __ldg(&pairs[2 * w]);
    int nb = __ldg(&pairs[2 * w + 1]);
    float4 ua = *((const float4*)(g_U + (size_t)na * 256) + lane);
    float4 ub = *((const float4*)(g_U + (size_t)nb * 256 + 128) + lane);
    float4 bv = *((const float4*)b3 + lane);
    float4 wv = *((const float4*)W4 + lane);
    float s = fmaxf(ua.x + ub.x + bv.x, 0.f) * wv.x
            + fmaxf(ua.y + ub.y + bv.y, 0.f) * wv.y
            + fmaxf(ua.z + ub.z + bv.z, 0.f) * wv.z
            + fmaxf(ua.w + ub.w + bv.w, 0.f) * wv.w;
#pragma unroll
    for (int o = 16; o > 0; o >>= 1)
        s += __shfl_xor_sync(0xffffffffu, s, o);
    if (lane == 0) out[w] = 1.0f / (1.0f + expf(-(s + b4[0])));
}

// ---------------- launch ----------------
extern "C" void kernel_launch(void* const* d_in, const int* in_sizes, int n_in,
                              void* d_out, int out_size) {
    const float* x    = (const float*)d_in[0];
    const int*   edge = (const int*)d_in[1];
    const int*   prs  = (const int*)d_in[2];
    const float* Wl1  = (const float*)d_in[3];
    const float* Wr1  = (const float*)d_in[4];
    const float* b1   = (const float*)d_in[5];
    const float* Wl2  = (const float*)d_in[6];
    const float* Wr2  = (const float*)d_in[7];
    const float* b2   = (const float*)d_in[8];
    const float* W3   = (const float*)d_in[9];
    const float* b3   = (const float*)d_in[10];
    const float* W4   = (const float*)d_in[11];
    const float* b4   = (const float*)d_in[12];
    float* out = (float*)d_out;

    const int E = in_sizes[1] / 2;
    const int P = in_sizes[2] / 2;
    const int M = N_NODES;
    const int* src = edge;
    const int* dst = edge + E;

    float* g_h1_p;  cudaGetSymbolAddress((void**)&g_h1_p, g_h1);
    int*   g_deg_p; cudaGetSymbolAddress((void**)&g_deg_p, g_deg);

    static int smem_set = 0;
    if (!smem_set) {
        cudaFuncSetAttribute(layer2u_kernel,
                             cudaFuncAttributeMaxDynamicSharedMemorySize, L2U_SMEM);
        smem_set = 1;
    }

    // CSR build (by dst)
    cudaMemsetAsync(g_deg_p, 0, N_NODES * sizeof(int));
    count_deg_kernel<<<(E + 255) / 256, 256>>>(dst, E);
    scan_deg_kernel<<<1, 1024>>>(E);
    fill_csr_kernel<<<(E + 255) / 256, 256>>>(src, dst, E);

    const int aggBlocks = (N_NODES * 32 + 255) / 256;
    const int mTiles = (M + BM - 1) / BM;

    // Layer 1
    agg_mean_kernel<<<aggBlocks, 256>>>(x, 0);
    layer_gemm_kernel<<<mTiles, 256>>>(x, Wl1, Wr1, b1, g_h1_p, M);
    // Layer 2 + U fused (h2 never leaves smem)
    agg_mean_kernel<<<aggBlocks, 256>>>(x, 1);
    layer2u_kernel<<<mTiles, 256, L2U_SMEM>>>(Wl2, Wr2, b2, W3, M);
    // Pair head
    pair_kernel<<<(P * 32 + 255) / 256, 256>>>(prs, b3, W4, b4, out, P);
}

// round 10
// speedup vs baseline: 1.7948x; 1.7948x over previous
#include <cuda_runtime.h>
#include <cuda_bf16.h>
#include <math.h>
#include <stdint.h>

#define N_NODES 50000
#define E_EDGES 500000
#define HDIM    128

// ---- scratch (device globals; no allocation in kernel_launch) ----
__device__ int   g_deg[N_NODES];
__device__ int   g_rowstart[N_NODES + 1];
__device__ int   g_cursor[N_NODES];
__device__ int   g_csr_src[E_EDGES];
__device__ float g_aggn[(size_t)N_NODES * HDIM];
__device__ float g_h1  [(size_t)N_NODES * HDIM];
__device__ float g_h2  [(size_t)N_NODES * HDIM];
__device__ float g_U   [(size_t)N_NODES * 256];
// split weights bf16 hi/lo, [n][k] row-major:
// L1 [128][256] @0, L2 [128][256] @32768, W3a [128][128] @65536, W3b [128][128] @81920
__device__ __nv_bfloat16 g_Wh[98304];
__device__ __nv_bfloat16 g_Wlo[98304];

__device__ __forceinline__ uint32_t smem_u32(const void* p) {
    uint32_t a;
    asm("{ .reg .u64 t; cvta.to.shared.u64 t, %1; cvt.u32.u64 %0, t; }" : "=r"(a) : "l"(p));
    return a;
}
#define LDSM_X4(r0, r1, r2, r3, a) \
    asm volatile("ldmatrix.sync.aligned.m8n8.x4.shared.b16 {%0,%1,%2,%3}, [%4];" \
        : "=r"(r0), "=r"(r1), "=r"(r2), "=r"(r3) : "r"(a))
#define MMA_BF16(c, a, b0, b1) \
    asm volatile("mma.sync.aligned.m16n8k16.row.col.f32.bf16.bf16.f32 " \
        "{%0,%1,%2,%3}, {%4,%5,%6,%7}, {%8,%9}, {%0,%1,%2,%3};" \
        : "+f"((c)[0]), "+f"((c)[1]), "+f"((c)[2]), "+f"((c)[3]) \
        : "r"((a)[0]), "r"((a)[1]), "r"((a)[2]), "r"((a)[3]), "r"(b0), "r"(b1))

// ---------------- CSR build ----------------
__global__ void count_deg_kernel(const int* __restrict__ dst, int E) {
    int i = blockIdx.x * blockDim.x + threadIdx.x;
    if (i < E) atomicAdd(&g_deg[dst[i]], 1);
}

__global__ void scan_deg_kernel(int E) {
    __shared__ int ssum[1024];
    int tid = threadIdx.x;
    const int chunk = (N_NODES + 1023) / 1024;
    int start = tid * chunk;
    int end = min(start + chunk, N_NODES);
    int s = 0;
    for (int i = start; i < end; i++) s += g_deg[i];
    ssum[tid] = s;
    __syncthreads();
    for (int d = 1; d < 1024; d <<= 1) {
        int v = (tid >= d) ? ssum[tid - d] : 0;
        __syncthreads();
        ssum[tid] += v;
        __syncthreads();
    }
    int run = ssum[tid] - s;
    for (int i = start; i < end; i++) {
        g_rowstart[i] = run;
        g_cursor[i]   = run;
        run += g_deg[i];
    }
    if (tid == 1023) g_rowstart[N_NODES] = E;
}

__global__ void fill_csr_kernel(const int* __restrict__ src,
                                const int* __restrict__ dst, int E) {
    int i = blockIdx.x * blockDim.x + threadIdx.x;
    if (i < E) {
        int p = atomicAdd(&g_cursor[dst[i]], 1);
        g_csr_src[p] = src[i];
    }
}

// ---------------- weight split: fp32 -> bf16 hi/lo ----------------
__global__ void split_w_kernel(const float* __restrict__ Wl1, const float* __restrict__ Wr1,
                               const float* __restrict__ Wl2, const float* __restrict__ Wr2,
                               const float* __restrict__ W3) {
    int idx = blockIdx.x * blockDim.x + threadIdx.x;
    if (idx >= 98304) return;
    float v;
    if (idx < 32768) {
        int n = idx >> 8, k = idx & 255;
        v = (k < 128) ? Wl1[n * 128 + k] : Wr1[n * 128 + (k - 128)];
    } else if (idx < 65536) {
        int j = idx - 32768;
        int n = j >> 8, k = j & 255;
        v = (k < 128) ? Wl2[n * 128 + k] : Wr2[n * 128 + (k - 128)];
    } else {
        int j = idx - 65536;
        int half = j >> 14;
        int jj = j & 16383;
        int n = jj >> 7, k = jj & 127;
        v = W3[n * 256 + half * 128 + k];
    }
    __nv_bfloat16 h = __float2bfloat16(v);
    __nv_bfloat16 l = __float2bfloat16(v - __bfloat162float(h));
    g_Wh[idx]  = h;
    g_Wlo[idx] = l;
}

// ---------------- mean aggregation: warp per node, MLP=8 ----------------
__global__ void agg_mean_kernel(const float* __restrict__ xin, int use_h1) {
    int gw   = (blockIdx.x * blockDim.x + threadIdx.x) >> 5;
    int lane = threadIdx.x & 31;
    if (gw >= N_NODES) return;
    const float* in = use_h1 ? g_h1 : xin;
    int s = g_rowstart[gw];
    int e = g_rowstart[gw + 1];
    float4 a0 = make_float4(0.f, 0.f, 0.f, 0.f);
    float4 a1 = make_float4(0.f, 0.f, 0.f, 0.f);
    float4 a2 = make_float4(0.f, 0.f, 0.f, 0.f);
    float4 a3 = make_float4(0.f, 0.f, 0.f, 0.f);
    int j = s;
    for (; j + 8 <= e; j += 8) {
        int s0 = g_csr_src[j],     s1 = g_csr_src[j + 1];
        int s2 = g_csr_src[j + 2], s3 = g_csr_src[j + 3];
        int s4 = g_csr_src[j + 4], s5 = g_csr_src[j + 5];
        int s6 = g_csr_src[j + 6], s7 = g_csr_src[j + 7];
        float4 v0 = *((const float4*)(in + (size_t)s0 * HDIM) + lane);
        float4 v1 = *((const float4*)(in + (size_t)s1 * HDIM) + lane);
        float4 v2 = *((const float4*)(in + (size_t)s2 * HDIM) + lane);
        float4 v3 = *((const float4*)(in + (size_t)s3 * HDIM) + lane);
        float4 v4 = *((const float4*)(in + (size_t)s4 * HDIM) + lane);
        float4 v5 = *((const float4*)(in + (size_t)s5 * HDIM) + lane);
        float4 v6 = *((const float4*)(in + (size_t)s6 * HDIM) + lane);
        float4 v7 = *((const float4*)(in + (size_t)s7 * HDIM) + lane);
        a0.x += v0.x; a0.y += v0.y; a0.z += v0.z; a0.w += v0.w;
        a1.x += v1.x; a1.y += v1.y; a1.z += v1.z; a1.w += v1.w;
        a2.x += v2.x; a2.y += v2.y; a2.z += v2.z; a2.w += v2.w;
        a3.x += v3.x; a3.y += v3.y; a3.z += v3.z; a3.w += v3.w;
        a0.x += v4.x; a0.y += v4.y; a0.z += v4.z; a0.w += v4.w;
        a1.x += v5.x; a1.y += v5.y; a1.z += v5.z; a1.w += v5.w;
        a2.x += v6.x; a2.y += v6.y; a2.z += v6.z; a2.w += v6.w;
        a3.x += v7.x; a3.y += v7.y; a3.z += v7.z; a3.w += v7.w;
    }
    for (; j + 2 <= e; j += 2) {
        int s0 = g_csr_src[j], s1 = g_csr_src[j + 1];
        float4 v0 = *((const float4*)(in + (size_t)s0 * HDIM) + lane);
        float4 v1 = *((const float4*)(in + (size_t)s1 * HDIM) + lane);
        a0.x += v0.x; a0.y += v0.y; a0.z += v0.z; a0.w += v0.w;
        a1.x += v1.x; a1.y += v1.y; a1.z += v1.z; a1.w += v1.w;
    }
    if (j < e) {
        int s0 = g_csr_src[j];
        float4 v0 = *((const float4*)(in + (size_t)s0 * HDIM) + lane);
        a0.x += v0.x; a0.y += v0.y; a0.z += v0.z; a0.w += v0.w;
    }
    float4 acc;
    acc.x = (a0.x + a1.x) + (a2.x + a3.x);
    acc.y = (a0.y + a1.y) + (a2.y + a3.y);
    acc.z = (a0.z + a1.z) + (a2.z + a3.z);
    acc.w = (a0.w + a1.w) + (a2.w + a3.w);
    float inv = 1.0f / (float)max(e - s, 1);
    acc.x *= inv; acc.y *= inv; acc.z *= inv; acc.w *= inv;
    *((float4*)(g_aggn + (size_t)gw * HDIM) + lane) = acc;
}

// ---------------- split-bf16 tensor-core GEMM (mma.sync HMMA) ----------------
// C[M x 128] = A[M x K] @ W[128 x K]^T (+bias, relu). K = nsrc*128, A = [A0 | A1].
// A = Ah + Al, W = Wh + Wl (bf16); C ~= AhWh + AhWl + AlWh, fp32 accum.
// Block: 256 thr (8 warps, 4m x 2n), tile 128x128, BK=32. Warp tile 32x64.
#define APAD 40   // bf16 elements per smem row (80B stride -> conflict-free ldmatrix)

__global__ void __launch_bounds__(256)
tgemm_kernel(const float* __restrict__ A0, const float* __restrict__ A1, int nsrc,
             int woff, int ldW, const float* __restrict__ bias,
             float* __restrict__ outp, int ldout, int dorelu, int M) {
    __shared__ __nv_bfloat16 Ah[128][APAD], Al[128][APAD];
    __shared__ __nv_bfloat16 Bh[128][APAD], Bl[128][APAD];

    int t = threadIdx.x, lane = t & 31, wid = t >> 5;
    int wm = wid >> 1;          // 0..3
    int wn = wid & 1;           // 0..1
    int m0 = blockIdx.x * 128;
    woff += blockIdx.y * 16384;
    int outcol = blockIdx.y * 128;

    float acc[2][8][4];
#pragma unroll
    for (int i = 0; i < 2; i++)
#pragma unroll
        for (int j = 0; j < 8; j++)
#pragma unroll
            for (int k = 0; k < 4; k++) acc[i][j][k] = 0.f;

    // ldmatrix thread-tile coords
    int tgrp = lane >> 3, trow = lane & 7;

    const int nch = nsrc * 4;
    for (int ch = 0; ch < nch; ch++) {
        const float* As = (ch >> 2) ? A1 : A0;
        int acol = (ch & 3) * 32;
        // stage A: 128 rows x 32 fp32 -> bf16 hi/lo
        {
            int row  = t >> 1;
            int cb   = (t & 1) * 16;
            int gr   = min(m0 + row, M - 1);
            const float4* src = (const float4*)(As + (size_t)gr * HDIM + acol + cb);
#pragma unroll
            for (int i = 0; i < 4; i++) {
                float4 f = src[i];
                __nv_bfloat16 h0 = __float2bfloat16(f.x), h1 = __float2bfloat16(f.y);
                __nv_bfloat16 h2 = __float2bfloat16(f.z), h3 = __float2bfloat16(f.w);
                __nv_bfloat16 l0 = __float2bfloat16(f.x - __bfloat162float(h0));
                __nv_bfloat16 l1 = __float2bfloat16(f.y - __bfloat162float(h1));
                __nv_bfloat16 l2 = __float2bfloat16(f.z - __bfloat162float(h2));
                __nv_bfloat16 l3 = __float2bfloat16(f.w - __bfloat162float(h3));
                uint2 hv, lv;
                hv.x = (uint32_t)__bfloat16_as_ushort(h0) | ((uint32_t)__bfloat16_as_ushort(h1) << 16);
                hv.y = (uint32_t)__bfloat16_as_ushort(h2) | ((uint32_t)__bfloat16_as_ushort(h3) << 16);
                lv.x = (uint32_t)__bfloat16_as_ushort(l0) | ((uint32_t)__bfloat16_as_ushort(l1) << 16);
                lv.y = (uint32_t)__bfloat16_as_ushort(l2) | ((uint32_t)__bfloat16_as_ushort(l3) << 16);
                *(uint2*)&Ah[row][cb + i * 4] = hv;
                *(uint2*)&Al[row][cb + i * 4] = lv;
            }
        }
        // stage B: 128 n-rows x 32 bf16 hi/lo from pre-split weights
        {
            int row = t >> 1;
            int cb  = (t & 1) * 16;
            const __nv_bfloat16* wh = g_Wh  + woff + (size_t)row * ldW + ch * 32 + cb;
            const __nv_bfloat16* wl = g_Wlo + woff + (size_t)row * ldW + ch * 32 + cb;
            *(uint4*)&Bh[row][cb]     = *(const uint4*)wh;
            *(uint4*)&Bh[row][cb + 8] = *(const uint4*)(wh + 8);
            *(uint4*)&Bl[row][cb]     = *(const uint4*)wl;
            *(uint4*)&Bl[row][cb + 8] = *(const uint4*)(wl + 8);
        }
        __syncthreads();
        // compute: 2 k-steps of 16
#pragma unroll
        for (int ks = 0; ks < 2; ks++) {
            int k0 = ks * 16;
            uint32_t ahf[2][4], alf[2][4];
#pragma unroll
            for (int mf = 0; mf < 2; mf++) {
                int ar = wm * 32 + mf * 16 + (tgrp & 1) * 8 + trow;
                int ac = k0 + (tgrp >> 1) * 8;
                LDSM_X4(ahf[mf][0], ahf[mf][1], ahf[mf][2], ahf[mf][3], smem_u32(&Ah[ar][ac]));
                LDSM_X4(alf[mf][0], alf[mf][1], alf[mf][2], alf[mf][3], smem_u32(&Al[ar][ac]));
            }
#pragma unroll
            for (int np = 0; np < 4; np++) {
                int br = wn * 64 + np * 16 + (tgrp >> 1) * 8 + trow;
                int bc = k0 + (tgrp & 1) * 8;
                uint32_t bh0, bh1, bh2, bh3, bl0, bl1, bl2, bl3;
                LDSM_X4(bh0, bh1, bh2, bh3, smem_u32(&Bh[br][bc]));
                LDSM_X4(bl0, bl1, bl2, bl3, smem_u32(&Bl[br][bc]));
#pragma unroll
                for (int mf = 0; mf < 2; mf++) {
                    MMA_BF16(acc[mf][np * 2],     ahf[mf], bh0, bh1);
                    MMA_BF16(acc[mf][np * 2],     ahf[mf], bl0, bl1);
                    MMA_BF16(acc[mf][np * 2],     alf[mf], bh0, bh1);
                    MMA_BF16(acc[mf][np * 2 + 1], ahf[mf], bh2, bh3);
                    MMA_BF16(acc[mf][np * 2 + 1], ahf[mf], bl2, bl3);
                    MMA_BF16(acc[mf][np * 2 + 1], alf[mf], bh2, bh3);
                }
            }
        }
        __syncthreads();
    }
    // epilogue: frags -> global (bias + relu)
    int qrow = lane >> 2;         // 0..7
    int qcol = (lane & 3) * 2;    // 0,2,4,6
#pragma unroll
    for (int mf = 0; mf < 2; mf++) {
#pragma unroll
        for (int nf = 0; nf < 8; nf++) {
            int n = wn * 64 + nf * 8 + qcol;
            float bx = 0.f, by = 0.f;
            if (bias) { bx = __ldg(bias + n); by = __ldg(bias + n + 1); }
#pragma unroll
            for (int half = 0; half < 2; half++) {
                int gr = m0 + wm * 32 + mf * 16 + half * 8 + qrow;
                if (gr < M) {
                    float v0 = acc[mf][nf][half * 2]     + bx;
                    float v1 = acc[mf][nf][half * 2 + 1] + by;
                    if (dorelu) { v0 = fmaxf(v0, 0.f); v1 = fmaxf(v1, 0.f); }
                    *(float2*)(outp + (size_t)gr * ldout + outcol + n) = make_float2(v0, v1);
                }
            }
        }
    }
}

// ---------------- pair head: sigmoid(W4 . relu(Ua[a]+Ub[b]+b3) + b4) ----------------
__global__ void __launch_bounds__(256)
pair_kernel(const int* __restrict__ pairs,
            const float* __restrict__ b3, const float* __restrict__ W4,
            const float* __restrict__ b4, float* __restrict__ out, int P) {
    int w    = (blockIdx.x * blockDim.x + threadIdx.x) >> 5;
    int lane = threadIdx.x & 31;
    if (w >= P) return;
    int na = __ldg(&pairs[2 * w]);
    int nb = __ldg(&pairs[2 * w + 1]);
    float4 ua = *((const float4*)(g_U + (size_t)na * 256) + lane);
    float4 ub = *((const float4*)(g_U + (size_t)nb * 256 + 128) + lane);
    float4 bv = *((const float4*)b3 + lane);
    float4 wv = *((const float4*)W4 + lane);
    float s = fmaxf(ua.x + ub.x + bv.x, 0.f) * wv.x
            + fmaxf(ua.y + ub.y + bv.y, 0.f) * wv.y
            + fmaxf(ua.z + ub.z + bv.z, 0.f) * wv.z
            + fmaxf(ua.w + ub.w + bv.w, 0.f) * wv.w;
#pragma unroll
    for (int o = 16; o > 0; o >>= 1)
        s += __shfl_xor_sync(0xffffffffu, s, o);
    if (lane == 0) out[w] = 1.0f / (1.0f + expf(-(s + b4[0])));
}

// ---------------- launch ----------------
extern "C" void kernel_launch(void* const* d_in, const int* in_sizes, int n_in,
                              void* d_out, int out_size) {
    const float* x    = (const float*)d_in[0];
    const int*   edge = (const int*)d_in[1];
    const int*   prs  = (const int*)d_in[2];
    const float* Wl1  = (const float*)d_in[3];
    const float* Wr1  = (const float*)d_in[4];
    const float* b1   = (const float*)d_in[5];
    const float* Wl2  = (const float*)d_in[6];
    const float* Wr2  = (const float*)d_in[7];
    const float* b2   = (const float*)d_in[8];
    const float* W3   = (const float*)d_in[9];
    const float* b3   = (const float*)d_in[10];
    const float* W4   = (const float*)d_in[11];
    const float* b4   = (const float*)d_in[12];
    float* out = (float*)d_out;

    const int E = in_sizes[1] / 2;
    const int P = in_sizes[2] / 2;
    const int M = N_NODES;
    const int* src = edge;
    const int* dst = edge + E;

    float* g_aggn_p; cudaGetSymbolAddress((void**)&g_aggn_p, g_aggn);
    float* g_h1_p;   cudaGetSymbolAddress((void**)&g_h1_p, g_h1);
    float* g_h2_p;   cudaGetSymbolAddress((void**)&g_h2_p, g_h2);
    float* g_U_p;    cudaGetSymbolAddress((void**)&g_U_p, g_U);
    int*   g_deg_p;  cudaGetSymbolAddress((void**)&g_deg_p, g_deg);

    // weight split + CSR build
    split_w_kernel<<<(98304 + 255) / 256, 256>>>(Wl1, Wr1, Wl2, Wr2, W3);
    cudaMemsetAsync(g_deg_p, 0, N_NODES * sizeof(int));
    count_deg_kernel<<<(E + 255) / 256, 256>>>(dst, E);
    scan_deg_kernel<<<1, 1024>>>(E);
    fill_csr_kernel<<<(E + 255) / 256, 256>>>(src, dst, E);

    const int aggBlocks = (N_NODES * 32 + 255) / 256;
    const int mTiles = (M + 127) / 128;   // 391

    // Layer 1: h1 = relu([agg|x] @ [Wl1|Wr1]^T + b1)
    agg_mean_kernel<<<aggBlocks, 256>>>(x, 0);
    tgemm_kernel<<<mTiles, 256>>>(g_aggn_p, x, 2, 0, 256, b1, g_h1_p, 128, 1, M);
    // Layer 2: h2 = relu([agg|h1] @ [Wl2|Wr2]^T + b2)
    agg_mean_kernel<<<aggBlocks, 256>>>(x, 1);
    tgemm_kernel<<<mTiles, 256>>>(g_aggn_p, g_h1_p, 2, 32768, 256, b2, g_h2_p, 128, 1, M);
    // U = h2 @ [W3a ; W3b]^T  (grid.y selects W3 half / output column block)
    tgemm_kernel<<<dim3(mTiles, 2), 256>>>(g_h2_p, (const float*)0, 1, 65536, 128,
                                           (const float*)0, g_U_p, 256, 0, M);
    // Pair head
    pair_kernel<<<(P * 32 + 255) / 256, 256>>>(prs, b3, W4, b4, out, P);
}

// round 11
// speedup vs baseline: 1.8993x; 1.0583x over previous
#include <cuda_runtime.h>
#include <cuda_bf16.h>
#include <math.h>
#include <stdint.h>

#define N_NODES 50000
#define E_EDGES 500000
#define HDIM    128

// ---- scratch (device globals; no allocation in kernel_launch) ----
__device__ int   g_deg[N_NODES];
__device__ int   g_rowstart[N_NODES + 1];
__device__ int   g_cursor[N_NODES];
__device__ int   g_csr_src[E_EDGES];
__device__ float g_aggn[(size_t)N_NODES * HDIM];
__device__ float g_h1  [(size_t)N_NODES * HDIM];
__device__ float g_U   [(size_t)N_NODES * 256];
// split weights bf16 hi/lo, [n][k] row-major:
// L1 [128][256] @0, L2 [128][256] @32768, W3a [128][128] @65536, W3b [128][128] @81920
__device__ __nv_bfloat16 g_Wh[98304];
__device__ __nv_bfloat16 g_Wlo[98304];

__device__ __forceinline__ uint32_t smem_u32(const void* p) {
    uint32_t a;
    asm("{ .reg .u64 t; cvta.to.shared.u64 t, %1; cvt.u32.u64 %0, t; }" : "=r"(a) : "l"(p));
    return a;
}
#define LDSM_X4(r0, r1, r2, r3, a) \
    asm volatile("ldmatrix.sync.aligned.m8n8.x4.shared.b16 {%0,%1,%2,%3}, [%4];" \
        : "=r"(r0), "=r"(r1), "=r"(r2), "=r"(r3) : "r"(a))
#define MMA_BF16(c, a, b0, b1) \
    asm volatile("mma.sync.aligned.m16n8k16.row.col.f32.bf16.bf16.f32 " \
        "{%0,%1,%2,%3}, {%4,%5,%6,%7}, {%8,%9}, {%0,%1,%2,%3};" \
        : "+f"((c)[0]), "+f"((c)[1]), "+f"((c)[2]), "+f"((c)[3]) \
        : "r"((a)[0]), "r"((a)[1]), "r"((a)[2]), "r"((a)[3]), "r"(b0), "r"(b1))

__device__ __forceinline__ void split_bf16(float v, __nv_bfloat16& h, __nv_bfloat16& l) {
    h = __float2bfloat16(v);
    l = __float2bfloat16(v - __bfloat162float(h));
}

// ---------------- CSR build ----------------
__global__ void count_deg_kernel(const int* __restrict__ dst, int E) {
    int i = blockIdx.x * blockDim.x + threadIdx.x;
    if (i < E) atomicAdd(&g_deg[dst[i]], 1);
}

__global__ void scan_deg_kernel(int E) {
    __shared__ int ssum[1024];
    int tid = threadIdx.x;
    const int chunk = (N_NODES + 1023) / 1024;
    int start = tid * chunk;
    int end = min(start + chunk, N_NODES);
    int s = 0;
    for (int i = start; i < end; i++) s += g_deg[i];
    ssum[tid] = s;
    __syncthreads();
    for (int d = 1; d < 1024; d <<= 1) {
        int v = (tid >= d) ? ssum[tid - d] : 0;
        __syncthreads();
        ssum[tid] += v;
        __syncthreads();
    }
    int run = ssum[tid] - s;
    for (int i = start; i < end; i++) {
        g_rowstart[i] = run;
        g_cursor[i]   = run;
        run += g_deg[i];
    }
    if (tid == 1023) g_rowstart[N_NODES] = E;
}

__global__ void fill_csr_kernel(const int* __restrict__ src,
                                const int* __restrict__ dst, int E) {
    int i = blockIdx.x * blockDim.x + threadIdx.x;
    if (i < E) {
        int p = atomicAdd(&g_cursor[dst[i]], 1);
        g_csr_src[p] = src[i];
    }
}

// ---------------- weight split: fp32 -> bf16 hi/lo ----------------
__global__ void split_w_kernel(const float* __restrict__ Wl1, const float* __restrict__ Wr1,
                               const float* __restrict__ Wl2, const float* __restrict__ Wr2,
                               const float* __restrict__ W3) {
    int idx = blockIdx.x * blockDim.x + threadIdx.x;
    if (idx >= 98304) return;
    float v;
    if (idx < 32768) {
        int n = idx >> 8, k = idx & 255;
        v = (k < 128) ? Wl1[n * 128 + k] : Wr1[n * 128 + (k - 128)];
    } else if (idx < 65536) {
        int j = idx - 32768;
        int n = j >> 8, k = j & 255;
        v = (k < 128) ? Wl2[n * 128 + k] : Wr2[n * 128 + (k - 128)];
    } else {
        int j = idx - 65536;
        int half = j >> 14;
        int jj = j & 16383;
        int n = jj >> 7, k = jj & 127;
        v = W3[n * 256 + half * 128 + k];
    }
    __nv_bfloat16 h, l;
    split_bf16(v, h, l);
    g_Wh[idx]  = h;
    g_Wlo[idx] = l;
}

// ---------------- mean aggregation: warp per node, MLP=8 ----------------
__global__ void agg_mean_kernel(const float* __restrict__ xin, int use_h1) {
    int gw   = (blockIdx.x * blockDim.x + threadIdx.x) >> 5;
    int lane = threadIdx.x & 31;
    if (gw >= N_NODES) return;
    const float* in = use_h1 ? g_h1 : xin;
    int s = g_rowstart[gw];
    int e = g_rowstart[gw + 1];
    float4 a0 = make_float4(0.f, 0.f, 0.f, 0.f);
    float4 a1 = make_float4(0.f, 0.f, 0.f, 0.f);
    float4 a2 = make_float4(0.f, 0.f, 0.f, 0.f);
    float4 a3 = make_float4(0.f, 0.f, 0.f, 0.f);
    int j = s;
    for (; j + 8 <= e; j += 8) {
        int s0 = g_csr_src[j],     s1 = g_csr_src[j + 1];
        int s2 = g_csr_src[j + 2], s3 = g_csr_src[j + 3];
        int s4 = g_csr_src[j + 4], s5 = g_csr_src[j + 5];
        int s6 = g_csr_src[j + 6], s7 = g_csr_src[j + 7];
        float4 v0 = *((const float4*)(in + (size_t)s0 * HDIM) + lane);
        float4 v1 = *((const float4*)(in + (size_t)s1 * HDIM) + lane);
        float4 v2 = *((const float4*)(in + (size_t)s2 * HDIM) + lane);
        float4 v3 = *((const float4*)(in + (size_t)s3 * HDIM) + lane);
        float4 v4 = *((const float4*)(in + (size_t)s4 * HDIM) + lane);
        float4 v5 = *((const float4*)(in + (size_t)s5 * HDIM) + lane);
        float4 v6 = *((const float4*)(in + (size_t)s6 * HDIM) + lane);
        float4 v7 = *((const float4*)(in + (size_t)s7 * HDIM) + lane);
        a0.x += v0.x; a0.y += v0.y; a0.z += v0.z; a0.w += v0.w;
        a1.x += v1.x; a1.y += v1.y; a1.z += v1.z; a1.w += v1.w;
        a2.x += v2.x; a2.y += v2.y; a2.z += v2.z; a2.w += v2.w;
        a3.x += v3.x; a3.y += v3.y; a3.z += v3.z; a3.w += v3.w;
        a0.x += v4.x; a0.y += v4.y; a0.z += v4.z; a0.w += v4.w;
        a1.x += v5.x; a1.y += v5.y; a1.z += v5.z; a1.w += v5.w;
        a2.x += v6.x; a2.y += v6.y; a2.z += v6.z; a2.w += v6.w;
        a3.x += v7.x; a3.y += v7.y; a3.z += v7.z; a3.w += v7.w;
    }
    for (; j + 2 <= e; j += 2) {
        int s0 = g_csr_src[j], s1 = g_csr_src[j + 1];
        float4 v0 = *((const float4*)(in + (size_t)s0 * HDIM) + lane);
        float4 v1 = *((const float4*)(in + (size_t)s1 * HDIM) + lane);
        a0.x += v0.x; a0.y += v0.y; a0.z += v0.z; a0.w += v0.w;
        a1.x += v1.x; a1.y += v1.y; a1.z += v1.z; a1.w += v1.w;
    }
    if (j < e) {
        int s0 = g_csr_src[j];
        float4 v0 = *((const float4*)(in + (size_t)s0 * HDIM) + lane);
        a0.x += v0.x; a0.y += v0.y; a0.z += v0.z; a0.w += v0.w;
    }
    float4 acc;
    acc.x = (a0.x + a1.x) + (a2.x + a3.x);
    acc.y = (a0.y + a1.y) + (a2.y + a3.y);
    acc.z = (a0.z + a1.z) + (a2.z + a3.z);
    acc.w = (a0.w + a1.w) + (a2.w + a3.w);
    float inv = 1.0f / (float)max(e - s, 1);
    acc.x *= inv; acc.y *= inv; acc.z *= inv; acc.w *= inv;
    *((float4*)(g_aggn + (size_t)gw * HDIM) + lane) = acc;
}

// ================= shared GEMM building blocks =================
// Block: 256 thr (8 warps, 4m x 2n), tile 128x128, BK=32. Warp tile 32x64.
#define APAD 40    // smem row stride (bf16) for 32-wide k tiles: 80B, conflict-free ldmatrix
#define HPAD 136   // smem row stride for the 128-wide h2 tile

// stage A chunk (128 rows x 32 fp32 -> bf16 hi/lo tiles)
__device__ __forceinline__ void stage_A(__nv_bfloat16* Ah, __nv_bfloat16* Al,
                                        const float* As, int m0, int acol, int M, int t) {
    int row = t >> 1;
    int cb  = (t & 1) * 16;
    int gr  = min(m0 + row, M - 1);
    const float4* src = (const float4*)(As + (size_t)gr * HDIM + acol + cb);
#pragma unroll
    for (int i = 0; i < 4; i++) {
        float4 f = src[i];
        __nv_bfloat16 h0, h1, h2, h3, l0, l1, l2, l3;
        split_bf16(f.x, h0, l0); split_bf16(f.y, h1, l1);
        split_bf16(f.z, h2, l2); split_bf16(f.w, h3, l3);
        uint2 hv, lv;
        hv.x = (uint32_t)__bfloat16_as_ushort(h0) | ((uint32_t)__bfloat16_as_ushort(h1) << 16);
        hv.y = (uint32_t)__bfloat16_as_ushort(h2) | ((uint32_t)__bfloat16_as_ushort(h3) << 16);
        lv.x = (uint32_t)__bfloat16_as_ushort(l0) | ((uint32_t)__bfloat16_as_ushort(l1) << 16);
        lv.y = (uint32_t)__bfloat16_as_ushort(l2) | ((uint32_t)__bfloat16_as_ushort(l3) << 16);
        *(uint2*)&Ah[row * APAD + cb + i * 4] = hv;
        *(uint2*)&Al[row * APAD + cb + i * 4] = lv;
    }
}

// stage B chunk (128 n-rows x 32 bf16 hi/lo from pre-split weights)
__device__ __forceinline__ void stage_B(__nv_bfloat16* Bh, __nv_bfloat16* Bl,
                                        int woff, int ldW, int kcol, int t) {
    int row = t >> 1;
    int cb  = (t & 1) * 16;
    const __nv_bfloat16* wh = g_Wh  + woff + (size_t)row * ldW + kcol + cb;
    const __nv_bfloat16* wl = g_Wlo + woff + (size_t)row * ldW + kcol + cb;
    *(uint4*)&Bh[row * APAD + cb]     = *(const uint4*)wh;
    *(uint4*)&Bh[row * APAD + cb + 8] = *(const uint4*)(wh + 8);
    *(uint4*)&Bl[row * APAD + cb]     = *(const uint4*)wl;
    *(uint4*)&Bl[row * APAD + cb + 8] = *(const uint4*)(wl + 8);
}

// one BK=32 compute step; A tiles at row-stride lda
__device__ __forceinline__ void mma_step(const __nv_bfloat16* Ah, const __nv_bfloat16* Al, int lda,
                                         int akbase,
                                         const __nv_bfloat16* Bh, const __nv_bfloat16* Bl,
                                         int wm, int wn, int tgrp, int trow,
                                         float acc[2][8][4]) {
#pragma unroll
    for (int ks = 0; ks < 2; ks++) {
        int ak = akbase + ks * 16;
        int bk = ks * 16;
        uint32_t ahf[2][4], alf[2][4];
#pragma unroll
        for (int mf = 0; mf < 2; mf++) {
            int ar = wm * 32 + mf * 16 + (tgrp & 1) * 8 + trow;
            int ac = ak + (tgrp >> 1) * 8;
            LDSM_X4(ahf[mf][0], ahf[mf][1], ahf[mf][2], ahf[mf][3], smem_u32(&Ah[ar * lda + ac]));
            LDSM_X4(alf[mf][0], alf[mf][1], alf[mf][2], alf[mf][3], smem_u32(&Al[ar * lda + ac]));
        }
#pragma unroll
        for (int np = 0; np < 4; np++) {
            int br = wn * 64 + np * 16 + (tgrp >> 1) * 8 + trow;
            int bc = bk + (tgrp & 1) * 8;
            uint32_t bh0, bh1, bh2, bh3, bl0, bl1, bl2, bl3;
            LDSM_X4(bh0, bh1, bh2, bh3, smem_u32(&Bh[br * APAD + bc]));
            LDSM_X4(bl0, bl1, bl2, bl3, smem_u32(&Bl[br * APAD + bc]));
#pragma unroll
            for (int mf = 0; mf < 2; mf++) {
                MMA_BF16(acc[mf][np * 2],     ahf[mf], bh0, bh1);
                MMA_BF16(acc[mf][np * 2],     ahf[mf], bl0, bl1);
                MMA_BF16(acc[mf][np * 2],     alf[mf], bh0, bh1);
                MMA_BF16(acc[mf][np * 2 + 1], ahf[mf], bh2, bh3);
                MMA_BF16(acc[mf][np * 2 + 1], ahf[mf], bl2, bl3);
                MMA_BF16(acc[mf][np * 2 + 1], alf[mf], bh2, bh3);
            }
        }
    }
}

// ---------------- layer-1 GEMM: h1 = relu([agg|x] @ [Wl1|Wr1]^T + b1) ----------------
__global__ void __launch_bounds__(256)
tgemm_kernel(const float* __restrict__ A0, const float* __restrict__ A1,
             int woff, const float* __restrict__ bias,
             float* __restrict__ outp, int M) {
    __shared__ __nv_bfloat16 Ah[128 * APAD], Al[128 * APAD];
    __shared__ __nv_bfloat16 Bh[128 * APAD], Bl[128 * APAD];
    int t = threadIdx.x, lane = t & 31, wid = t >> 5;
    int wm = wid >> 1, wn = wid & 1;
    int m0 = blockIdx.x * 128;
    float acc[2][8][4];
#pragma unroll
    for (int i = 0; i < 2; i++)
#pragma unroll
        for (int j = 0; j < 8; j++)
#pragma unroll
            for (int k = 0; k < 4; k++) acc[i][j][k] = 0.f;
    int tgrp = lane >> 3, trow = lane & 7;

    for (int ch = 0; ch < 8; ch++) {
        const float* As = (ch >> 2) ? A1 : A0;
        stage_A(Ah, Al, As, m0, (ch & 3) * 32, M, t);
        stage_B(Bh, Bl, woff, 256, ch * 32, t);
        __syncthreads();
        mma_step(Ah, Al, APAD, 0, Bh, Bl, wm, wn, tgrp, trow, acc);
        __syncthreads();
    }
    int qrow = lane >> 2, qcol = (lane & 3) * 2;
#pragma unroll
    for (int mf = 0; mf < 2; mf++)
#pragma unroll
        for (int nf = 0; nf < 8; nf++) {
            int n = wn * 64 + nf * 8 + qcol;
            float bx = __ldg(bias + n), by = __ldg(bias + n + 1);
#pragma unroll
            for (int half = 0; half < 2; half++) {
                int gr = m0 + wm * 32 + mf * 16 + half * 8 + qrow;
                if (gr < M) {
                    float v0 = fmaxf(acc[mf][nf][half * 2]     + bx, 0.f);
                    float v1 = fmaxf(acc[mf][nf][half * 2 + 1] + by, 0.f);
                    *(float2*)(outp + (size_t)gr * HDIM + n) = make_float2(v0, v1);
                }
            }
        }
}

// ---------------- fused layer-2 + U: h2 stays in smem ----------------
// dyn smem: Bh[128*APAD] Bl[128*APAD] | X: phaseA Ah/Al[128*APAD each] -> phaseB H2h/H2l[128*HPAD each]
#define L2U_SMEM ((2 * 128 * APAD + 2 * 128 * HPAD) * 2)   // 90112 B
__global__ void __launch_bounds__(256)
layer2u_kernel(const float* __restrict__ b2, int M) {
    extern __shared__ __nv_bfloat16 sm[];
    __nv_bfloat16* Bh  = sm;
    __nv_bfloat16* Bl  = Bh + 128 * APAD;
    __nv_bfloat16* Ah  = Bl + 128 * APAD;
    __nv_bfloat16* Al  = Ah + 128 * APAD;
    __nv_bfloat16* H2h = Ah;                    // overlaps Ah/Al after phase A
    __nv_bfloat16* H2l = H2h + 128 * HPAD;

    int t = threadIdx.x, lane = t & 31, wid = t >> 5;
    int wm = wid >> 1, wn = wid & 1;
    int m0 = blockIdx.x * 128;
    int tgrp = lane >> 3, trow = lane & 7;
    int qrow = lane >> 2, qcol = (lane & 3) * 2;

    float acc[2][8][4];
#pragma unroll
    for (int i = 0; i < 2; i++)
#pragma unroll
        for (int j = 0; j < 8; j++)
#pragma unroll
            for (int k = 0; k < 4; k++) acc[i][j][k] = 0.f;

    // ---- phase A: h2 = relu([agg|h1] @ [Wl2|Wr2]^T + b2) ----
    for (int ch = 0; ch < 8; ch++) {
        const float* As = (ch >> 2) ? g_h1 : g_aggn;
        stage_A(Ah, Al, As, m0, (ch & 3) * 32, M, t);
        stage_B(Bh, Bl, 32768, 256, ch * 32, t);
        __syncthreads();
        mma_step(Ah, Al, APAD, 0, Bh, Bl, wm, wn, tgrp, trow, acc);
        __syncthreads();
    }
    // write h2 (bias+relu) into smem as bf16 hi/lo (overwrites Ah/Al region)
#pragma unroll
    for (int mf = 0; mf < 2; mf++)
#pragma unroll
        for (int nf = 0; nf < 8; nf++) {
            int n = wn * 64 + nf * 8 + qcol;
            float bx = __ldg(b2 + n), by = __ldg(b2 + n + 1);
#pragma unroll
            for (int half = 0; half < 2; half++) {
                int row = wm * 32 + mf * 16 + half * 8 + qrow;
                float v0 = fmaxf(acc[mf][nf][half * 2]     + bx, 0.f);
                float v1 = fmaxf(acc[mf][nf][half * 2 + 1] + by, 0.f);
                __nv_bfloat16 h0, l0, h1, l1;
                split_bf16(v0, h0, l0);
                split_bf16(v1, h1, l1);
                H2h[row * HPAD + n]     = h0;
                H2h[row * HPAD + n + 1] = h1;
                H2l[row * HPAD + n]     = l0;
                H2l[row * HPAD + n + 1] = l1;
            }
        }
    __syncthreads();

    // ---- phase B: U[:, y*128..] = h2 @ W3y^T ----
    for (int y = 0; y < 2; y++) {
#pragma unroll
        for (int i = 0; i < 2; i++)
#pragma unroll
            for (int j = 0; j < 8; j++)
#pragma unroll
                for (int k = 0; k < 4; k++) acc[i][j][k] = 0.f;
        for (int ch = 0; ch < 4; ch++) {
            stage_B(Bh, Bl, 65536 + y * 16384, 128, ch * 32, t);
            __syncthreads();
            mma_step(H2h, H2l, HPAD, ch * 32, Bh, Bl, wm, wn, tgrp, trow, acc);
            __syncthreads();
        }
#pragma unroll
        for (int mf = 0; mf < 2; mf++)
#pragma unroll
            for (int nf = 0; nf < 8; nf++) {
                int n = wn * 64 + nf * 8 + qcol;
#pragma unroll
                for (int half = 0; half < 2; half++) {
                    int gr = m0 + wm * 32 + mf * 16 + half * 8 + qrow;
                    if (gr < M) {
                        float v0 = acc[mf][nf][half * 2];
                        float v1 = acc[mf][nf][half * 2 + 1];
                        *(float2*)(g_U + (size_t)gr * 256 + y * 128 + n) = make_float2(v0, v1);
                    }
                }
            }
    }
}

// ---------------- pair head: sigmoid(W4 . relu(Ua[a]+Ub[b]+b3) + b4) ----------------
__global__ void __launch_bounds__(256)
pair_kernel(const int* __restrict__ pairs,
            const float* __restrict__ b3, const float* __restrict__ W4,
            const float* __restrict__ b4, float* __restrict__ out, int P) {
    int w    = (blockIdx.x * blockDim.x + threadIdx.x) >> 5;
    int lane = threadIdx.x & 31;
    if (w >= P) return;
    int na = __ldg(&pairs[2 * w]);
    int nb = __ldg(&pairs[2 * w + 1]);
    float4 ua = *((const float4*)(g_U + (size_t)na * 256) + lane);
    float4 ub = *((const float4*)(g_U + (size_t)nb * 256 + 128) + lane);
    float4 bv = *((const float4*)b3 + lane);
    float4 wv = *((const float4*)W4 + lane);
    float s = fmaxf(ua.x + ub.x + bv.x, 0.f) * wv.x
            + fmaxf(ua.y + ub.y + bv.y, 0.f) * wv.y
            + fmaxf(ua.z + ub.z + bv.z, 0.f) * wv.z
            + fmaxf(ua.w + ub.w + bv.w, 0.f) * wv.w;
#pragma unroll
    for (int o = 16; o > 0; o >>= 1)
        s += __shfl_xor_sync(0xffffffffu, s, o);
    if (lane == 0) out[w] = 1.0f / (1.0f + __expf(-(s + b4[0])));
}

// ---------------- launch ----------------
extern "C" void kernel_launch(void* const* d_in, const int* in_sizes, int n_in,
                              void* d_out, int out_size) {
    const float* x    = (const float*)d_in[0];
    const int*   edge = (const int*)d_in[1];
    const int*   prs  = (const int*)d_in[2];
    const float* Wl1  = (const float*)d_in[3];
    const float* Wr1  = (const float*)d_in[4];
    const float* b1   = (const float*)d_in[5];
    const float* Wl2  = (const float*)d_in[6];
    const float* Wr2  = (const float*)d_in[7];
    const float* b2   = (const float*)d_in[8];
    const float* W3   = (const float*)d_in[9];
    const float* b3   = (const float*)d_in[10];
    const float* W4   = (const float*)d_in[11];
    const float* b4   = (const float*)d_in[12];
    float* out = (float*)d_out;

    const int E = in_sizes[1] / 2;
    const int P = in_sizes[2] / 2;
    const int M = N_NODES;
    const int* src = edge;
    const int* dst = edge + E;

    float* g_aggn_p; cudaGetSymbolAddress((void**)&g_aggn_p, g_aggn);
    float* g_h1_p;   cudaGetSymbolAddress((void**)&g_h1_p, g_h1);
    int*   g_deg_p;  cudaGetSymbolAddress((void**)&g_deg_p, g_deg);

    cudaFuncSetAttribute(layer2u_kernel, cudaFuncAttributeMaxDynamicSharedMemorySize, L2U_SMEM);

    // weight split + CSR build
    split_w_kernel<<<(98304 + 255) / 256, 256>>>(Wl1, Wr1, Wl2, Wr2, W3);
    cudaMemsetAsync(g_deg_p, 0, N_NODES * sizeof(int));
    count_deg_kernel<<<(E + 255) / 256, 256>>>(dst, E);
    scan_deg_kernel<<<1, 1024>>>(E);
    fill_csr_kernel<<<(E + 255) / 256, 256>>>(src, dst, E);

    const int aggBlocks = (N_NODES * 32 + 255) / 256;
    const int mTiles = (M + 127) / 128;   // 391

    // Layer 1
    agg_mean_kernel<<<aggBlocks, 256>>>(x, 0);
    tgemm_kernel<<<mTiles, 256>>>(g_aggn_p, x, 0, b1, g_h1_p, M);
    // Layer 2 + U fused (h2 never leaves smem)
    agg_mean_kernel<<<aggBlocks, 256>>>(x, 1);
    layer2u_kernel<<<mTiles, 256, L2U_SMEM>>>(b2, M);
    // Pair head
    pair_kernel<<<(P * 32 + 255) / 256, 256>>>(prs, b3, W4, b4, out, P);
}

// round 12
// speedup vs baseline: 2.0727x; 1.0913x over previous
#include <cuda_runtime.h>
#include <cuda_bf16.h>
#include <math.h>
#include <stdint.h>

#define N_NODES 50000
#define E_EDGES 500000
#define HDIM    128

// ---- scratch (device globals; no allocation in kernel_launch) ----
__device__ int   g_deg[N_NODES];
__device__ int   g_rowstart[N_NODES + 1];
__device__ int   g_cursor[N_NODES];
__device__ int   g_csr_src[E_EDGES];
__device__ float g_h1  [(size_t)N_NODES * HDIM];
__device__ float g_U   [(size_t)N_NODES * 256];
// pre-split operands (bf16 hi/lo)
__device__ __nv_bfloat16 g_aggh[(size_t)N_NODES * HDIM];
__device__ __nv_bfloat16 g_aggl[(size_t)N_NODES * HDIM];
__device__ __nv_bfloat16 g_h1h [(size_t)N_NODES * HDIM];
__device__ __nv_bfloat16 g_h1l [(size_t)N_NODES * HDIM];
// split weights bf16 hi/lo, [n][k] row-major:
// L1 [128][256] @0, L2 [128][256] @32768, W3a [128][128] @65536, W3b [128][128] @81920
__device__ __nv_bfloat16 g_Wh[98304];
__device__ __nv_bfloat16 g_Wlo[98304];

__device__ __forceinline__ uint32_t smem_u32(const void* p) {
    uint32_t a;
    asm("{ .reg .u64 t; cvta.to.shared.u64 t, %1; cvt.u32.u64 %0, t; }" : "=r"(a) : "l"(p));
    return a;
}
#define LDSM_X4(r0, r1, r2, r3, a) \
    asm volatile("ldmatrix.sync.aligned.m8n8.x4.shared.b16 {%0,%1,%2,%3}, [%4];" \
        : "=r"(r0), "=r"(r1), "=r"(r2), "=r"(r3) : "r"(a))
#define MMA_BF16(c, a, b0, b1) \
    asm volatile("mma.sync.aligned.m16n8k16.row.col.f32.bf16.bf16.f32 " \
        "{%0,%1,%2,%3}, {%4,%5,%6,%7}, {%8,%9}, {%0,%1,%2,%3};" \
        : "+f"((c)[0]), "+f"((c)[1]), "+f"((c)[2]), "+f"((c)[3]) \
        : "r"((a)[0]), "r"((a)[1]), "r"((a)[2]), "r"((a)[3]), "r"(b0), "r"(b1))
#define CP16(dst, src) \
    asm volatile("cp.async.ca.shared.global [%0], [%1], 16;" :: "r"(dst), "l"(src))
#define CP_COMMIT() asm volatile("cp.async.commit_group;" ::: "memory")
#define CP_WAIT1()  asm volatile("cp.async.wait_group 1;" ::: "memory")

__device__ __forceinline__ void split_bf16(float v, __nv_bfloat16& h, __nv_bfloat16& l) {
    h = __float2bfloat16(v);
    l = __float2bfloat16(v - __bfloat162float(h));
}
__device__ __forceinline__ uint32_t pack2(__nv_bfloat16 a, __nv_bfloat16 b) {
    return (uint32_t)__bfloat16_as_ushort(a) | ((uint32_t)__bfloat16_as_ushort(b) << 16);
}

// ---------------- CSR build ----------------
__global__ void count_deg_kernel(const int* __restrict__ dst, int E) {
    int i = blockIdx.x * blockDim.x + threadIdx.x;
    if (i < E) atomicAdd(&g_deg[dst[i]], 1);
}

__global__ void scan_deg_kernel(int E) {
    __shared__ int ssum[1024];
    int tid = threadIdx.x;
    const int chunk = (N_NODES + 1023) / 1024;
    int start = tid * chunk;
    int end = min(start + chunk, N_NODES);
    int s = 0;
    for (int i = start; i < end; i++) s += g_deg[i];
    ssum[tid] = s;
    __syncthreads();
    for (int d = 1; d < 1024; d <<= 1) {
        int v = (tid >= d) ? ssum[tid - d] : 0;
        __syncthreads();
        ssum[tid] += v;
        __syncthreads();
    }
    int run = ssum[tid] - s;
    for (int i = start; i < end; i++) {
        g_rowstart[i] = run;
        g_cursor[i]   = run;
        run += g_deg[i];
    }
    if (tid == 1023) g_rowstart[N_NODES] = E;
}

__global__ void fill_csr_kernel(const int* __restrict__ src,
                                const int* __restrict__ dst, int E) {
    int i = blockIdx.x * blockDim.x + threadIdx.x;
    if (i < E) {
        int p = atomicAdd(&g_cursor[dst[i]], 1);
        g_csr_src[p] = src[i];
    }
}

// ---------------- weight split: fp32 -> bf16 hi/lo ----------------
__global__ void split_w_kernel(const float* __restrict__ Wl1, const float* __restrict__ Wr1,
                               const float* __restrict__ Wl2, const float* __restrict__ Wr2,
                               const float* __restrict__ W3) {
    int idx = blockIdx.x * blockDim.x + threadIdx.x;
    if (idx >= 98304) return;
    float v;
    if (idx < 32768) {
        int n = idx >> 8, k = idx & 255;
        v = (k < 128) ? Wl1[n * 128 + k] : Wr1[n * 128 + (k - 128)];
    } else if (idx < 65536) {
        int j = idx - 32768;
        int n = j >> 8, k = j & 255;
        v = (k < 128) ? Wl2[n * 128 + k] : Wr2[n * 128 + (k - 128)];
    } else {
        int j = idx - 65536;
        int half = j >> 14;
        int jj = j & 16383;
        int n = jj >> 7, k = jj & 127;
        v = W3[n * 256 + half * 128 + k];
    }
    __nv_bfloat16 h, l;
    split_bf16(v, h, l);
    g_Wh[idx]  = h;
    g_Wlo[idx] = l;
}

// ---------------- mean aggregation: warp per node, MLP=8; writes split bf16 ----------------
__global__ void agg_mean_kernel(const float* __restrict__ xin, int use_h1) {
    int gw   = (blockIdx.x * blockDim.x + threadIdx.x) >> 5;
    int lane = threadIdx.x & 31;
    if (gw >= N_NODES) return;
    const float* in = use_h1 ? g_h1 : xin;
    int s = g_rowstart[gw];
    int e = g_rowstart[gw + 1];
    float4 a0 = make_float4(0.f, 0.f, 0.f, 0.f);
    float4 a1 = make_float4(0.f, 0.f, 0.f, 0.f);
    float4 a2 = make_float4(0.f, 0.f, 0.f, 0.f);
    float4 a3 = make_float4(0.f, 0.f, 0.f, 0.f);
    int j = s;
    for (; j + 8 <= e; j += 8) {
        int s0 = g_csr_src[j],     s1 = g_csr_src[j + 1];
        int s2 = g_csr_src[j + 2], s3 = g_csr_src[j + 3];
        int s4 = g_csr_src[j + 4], s5 = g_csr_src[j + 5];
        int s6 = g_csr_src[j + 6], s7 = g_csr_src[j + 7];
        float4 v0 = *((const float4*)(in + (size_t)s0 * HDIM) + lane);
        float4 v1 = *((const float4*)(in + (size_t)s1 * HDIM) + lane);
        float4 v2 = *((const float4*)(in + (size_t)s2 * HDIM) + lane);
        float4 v3 = *((const float4*)(in + (size_t)s3 * HDIM) + lane);
        float4 v4 = *((const float4*)(in + (size_t)s4 * HDIM) + lane);
        float4 v5 = *((const float4*)(in + (size_t)s5 * HDIM) + lane);
        float4 v6 = *((const float4*)(in + (size_t)s6 * HDIM) + lane);
        float4 v7 = *((const float4*)(in + (size_t)s7 * HDIM) + lane);
        a0.x += v0.x; a0.y += v0.y; a0.z += v0.z; a0.w += v0.w;
        a1.x += v1.x; a1.y += v1.y; a1.z += v1.z; a1.w += v1.w;
        a2.x += v2.x; a2.y += v2.y; a2.z += v2.z; a2.w += v2.w;
        a3.x += v3.x; a3.y += v3.y; a3.z += v3.z; a3.w += v3.w;
        a0.x += v4.x; a0.y += v4.y; a0.z += v4.z; a0.w += v4.w;
        a1.x += v5.x; a1.y += v5.y; a1.z += v5.z; a1.w += v5.w;
        a2.x += v6.x; a2.y += v6.y; a2.z += v6.z; a2.w += v6.w;
        a3.x += v7.x; a3.y += v7.y; a3.z += v7.z; a3.w += v7.w;
    }
    for (; j + 2 <= e; j += 2) {
        int s0 = g_csr_src[j], s1 = g_csr_src[j + 1];
        float4 v0 = *((const float4*)(in + (size_t)s0 * HDIM) + lane);
        float4 v1 = *((const float4*)(in + (size_t)s1 * HDIM) + lane);
        a0.x += v0.x; a0.y += v0.y; a0.z += v0.z; a0.w += v0.w;
        a1.x += v1.x; a1.y += v1.y; a1.z += v1.z; a1.w += v1.w;
    }
    if (j < e) {
        int s0 = g_csr_src[j];
        float4 v0 = *((const float4*)(in + (size_t)s0 * HDIM) + lane);
        a0.x += v0.x; a0.y += v0.y; a0.z += v0.z; a0.w += v0.w;
    }
    float4 acc;
    acc.x = (a0.x + a1.x) + (a2.x + a3.x);
    acc.y = (a0.y + a1.y) + (a2.y + a3.y);
    acc.z = (a0.z + a1.z) + (a2.z + a3.z);
    acc.w = (a0.w + a1.w) + (a2.w + a3.w);
    float inv = 1.0f / (float)max(e - s, 1);
    acc.x *= inv; acc.y *= inv; acc.z *= inv; acc.w *= inv;
    __nv_bfloat16 h0, l0, h1, l1, h2, l2, h3, l3;
    split_bf16(acc.x, h0, l0); split_bf16(acc.y, h1, l1);
    split_bf16(acc.z, h2, l2); split_bf16(acc.w, h3, l3);
    uint2 hv = make_uint2(pack2(h0, h1), pack2(h2, h3));
    uint2 lv = make_uint2(pack2(l0, l1), pack2(l2, l3));
    *((uint2*)(g_aggh + (size_t)gw * HDIM) + lane) = hv;
    *((uint2*)(g_aggl + (size_t)gw * HDIM) + lane) = lv;
}

// ================= GEMM building blocks =================
// Block: 256 thr (8 warps, 4m x 2n), tile 128x128, BK=32. Warp tile 32x64.
#define APAD 40    // 80B smem row stride, conflict-free ldmatrix, 16B aligned rows
#define HPAD 136   // 272B row stride for h2 smem tile
#define TILEB 10240                       // one 128xAPAD bf16 tile
#define STAGEB (2 * TILEB)                // Ah+Al or Bh+Bl per stage

// cp.async issue of one 128x32 bf16 tile pair (hi/lo), 2x16B per thread each
__device__ __forceinline__ void issue_tile(uint32_t dh, uint32_t dl,
                                           const __nv_bfloat16* sh, const __nv_bfloat16* sl,
                                           size_t rstride, int rclamp, int coff, int t) {
#pragma unroll
    for (int it = 0; it < 2; it++) {
        int q = t + it * 256;
        int row = q >> 2, u = q & 3;
        int gr = min(row, rclamp);
        const __nv_bfloat16* ph = sh + (size_t)gr * rstride + coff + u * 8;
        const __nv_bfloat16* pl = sl + (size_t)gr * rstride + coff + u * 8;
        CP16(dh + row * 80 + u * 16, ph);
        CP16(dl + row * 80 + u * 16, pl);
    }
}

// one BK=32 compute step; A at row-stride lda (elements), B at APAD
__device__ __forceinline__ void mma_step(const __nv_bfloat16* Ah, const __nv_bfloat16* Al, int lda,
                                         int akbase,
                                         const __nv_bfloat16* Bh, const __nv_bfloat16* Bl,
                                         int wm, int wn, int tgrp, int trow,
                                         float acc[2][8][4]) {
#pragma unroll
    for (int ks = 0; ks < 2; ks++) {
        int ak = akbase + ks * 16;
        int bk = ks * 16;
        uint32_t ahf[2][4], alf[2][4];
#pragma unroll
        for (int mf = 0; mf < 2; mf++) {
            int ar = wm * 32 + mf * 16 + (tgrp & 1) * 8 + trow;
            int ac = ak + (tgrp >> 1) * 8;
            LDSM_X4(ahf[mf][0], ahf[mf][1], ahf[mf][2], ahf[mf][3], smem_u32(&Ah[ar * lda + ac]));
            LDSM_X4(alf[mf][0], alf[mf][1], alf[mf][2], alf[mf][3], smem_u32(&Al[ar * lda + ac]));
        }
#pragma unroll
        for (int np = 0; np < 4; np++) {
            int br = wn * 64 + np * 16 + (tgrp >> 1) * 8 + trow;
            int bc = bk + (tgrp & 1) * 8;
            uint32_t bh0, bh1, bh2, bh3, bl0, bl1, bl2, bl3;
            LDSM_X4(bh0, bh1, bh2, bh3, smem_u32(&Bh[br * APAD + bc]));
            LDSM_X4(bl0, bl1, bl2, bl3, smem_u32(&Bl[br * APAD + bc]));
#pragma unroll
            for (int mf = 0; mf < 2; mf++) {
                MMA_BF16(acc[mf][np * 2],     ahf[mf], bh0, bh1);
                MMA_BF16(acc[mf][np * 2],     ahf[mf], bl0, bl1);
                MMA_BF16(acc[mf][np * 2],     alf[mf], bh0, bh1);
                MMA_BF16(acc[mf][np * 2 + 1], ahf[mf], bh2, bh3);
                MMA_BF16(acc[mf][np * 2 + 1], ahf[mf], bl2, bl3);
                MMA_BF16(acc[mf][np * 2 + 1], alf[mf], bh2, bh3);
            }
        }
    }
}

// ---------------- layer-1 GEMM: h1 = relu([agg|x] @ [Wl1|Wr1]^T + b1) ----------------
// dyn smem: B stages [0,2*STAGEB) | A stages [2*STAGEB, 4*STAGEB)  = 81920 B
#define T1_SMEM (4 * STAGEB)
__global__ void __launch_bounds__(256)
tgemm_kernel(const float* __restrict__ x, const float* __restrict__ bias,
             float* __restrict__ outp, int M) {
    extern __shared__ __nv_bfloat16 sm[];
    uint32_t sb = smem_u32(sm);
    // stage s: B at sb + s*STAGEB (Bh, Bl); A at sb + 2*STAGEB + s*STAGEB (Ah, Al)
    int t = threadIdx.x, lane = t & 31, wid = t >> 5;
    int wm = wid >> 1, wn = wid & 1;
    int m0 = blockIdx.x * 128;
    int rclamp = M - 1 - m0;
    int tgrp = lane >> 3, trow = lane & 7;

    float acc[2][8][4];
#pragma unroll
    for (int i = 0; i < 2; i++)
#pragma unroll
        for (int j = 0; j < 8; j++)
#pragma unroll
            for (int k = 0; k < 4; k++) acc[i][j][k] = 0.f;

    const __nv_bfloat16* aggh = g_aggh + (size_t)m0 * HDIM;
    const __nv_bfloat16* aggl = g_aggl + (size_t)m0 * HDIM;

    // issue chunk 0 (agg, async)
    issue_tile(sb + 2 * STAGEB, sb + 2 * STAGEB + TILEB, aggh, aggl, HDIM, rclamp, 0, t);
    issue_tile(sb, sb + TILEB, g_Wh, g_Wlo, 256, 127, 0, t);
    CP_COMMIT();

    for (int ch = 0; ch < 8; ch++) {
        int cur = ch & 1, nxt = (ch + 1) & 1;
        float4 xr[4];
        bool havex = false;
        if (ch + 1 < 8) {
            int nc = ch + 1;
            int acol = (nc & 3) * 32;
            if (nc < 4) {
                issue_tile(sb + 2 * STAGEB + nxt * STAGEB, sb + 2 * STAGEB + nxt * STAGEB + TILEB,
                           aggh, aggl, HDIM, rclamp, acol, t);
            } else {
                // x chunk: prefetch fp32 into regs, convert+store after this chunk's mma
#pragma unroll
                for (int it = 0; it < 2; it++) {
                    int q = t + it * 256;
                    int row = q >> 2, u = q & 3;
                    int gr = min(m0 + row, M - 1);
                    const float4* p = (const float4*)(x + (size_t)gr * HDIM + acol + u * 8);
                    xr[it * 2]     = p[0];
                    xr[it * 2 + 1] = p[1];
                }
                havex = true;
            }
            issue_tile(sb + nxt * STAGEB, sb + nxt * STAGEB + TILEB, g_Wh, g_Wlo, 256, 127, nc * 32, t);
        }
        CP_COMMIT();
        CP_WAIT1();
        __syncthreads();
        mma_step(sm + (2 * STAGEB + cur * STAGEB) / 2, sm + (2 * STAGEB + cur * STAGEB + TILEB) / 2,
                 APAD, 0,
                 sm + (cur * STAGEB) / 2, sm + (cur * STAGEB + TILEB) / 2,
                 wm, wn, tgrp, trow, acc);
        __syncthreads();
        if (havex) {
            __nv_bfloat16* Ahn = sm + (2 * STAGEB + nxt * STAGEB) / 2;
            __nv_bfloat16* Aln = Ahn + TILEB / 2;
#pragma unroll
            for (int it = 0; it < 2; it++) {
                int q = t + it * 256;
                int row = q >> 2, u = q & 3;
                const float* f = (const float*)&xr[it * 2];
                __nv_bfloat16 hh[8], ll[8];
#pragma unroll
                for (int i = 0; i < 8; i++) split_bf16(f[i], hh[i], ll[i]);
                uint4 hv = make_uint4(pack2(hh[0], hh[1]), pack2(hh[2], hh[3]),
                                      pack2(hh[4], hh[5]), pack2(hh[6], hh[7]));
                uint4 lv = make_uint4(pack2(ll[0], ll[1]), pack2(ll[2], ll[3]),
                                      pack2(ll[4], ll[5]), pack2(ll[6], ll[7]));
                *(uint4*)&Ahn[row * APAD + u * 8] = hv;
                *(uint4*)&Aln[row * APAD + u * 8] = lv;
            }
        }
    }
    // epilogue: bias+relu -> h1 fp32 AND pre-split bf16
    int qrow = lane >> 2, qcol = (lane & 3) * 2;
#pragma unroll
    for (int mf = 0; mf < 2; mf++)
#pragma unroll
        for (int nf = 0; nf < 8; nf++) {
            int n = wn * 64 + nf * 8 + qcol;
            float bx = __ldg(bias + n), by = __ldg(bias + n + 1);
#pragma unroll
            for (int half = 0; half < 2; half++) {
                int gr = m0 + wm * 32 + mf * 16 + half * 8 + qrow;
                if (gr < M) {
                    float v0 = fmaxf(acc[mf][nf][half * 2]     + bx, 0.f);
                    float v1 = fmaxf(acc[mf][nf][half * 2 + 1] + by, 0.f);
                    *(float2*)(outp + (size_t)gr * HDIM + n) = make_float2(v0, v1);
                    __nv_bfloat16 h0, l0, h1b, l1b;
                    split_bf16(v0, h0, l0);
                    split_bf16(v1, h1b, l1b);
                    *(uint32_t*)(g_h1h + (size_t)gr * HDIM + n) = pack2(h0, h1b);
                    *(uint32_t*)(g_h1l + (size_t)gr * HDIM + n) = pack2(l0, l1b);
                }
            }
        }
}

// ---------------- fused layer-2 + U: h2 stays in smem ----------------
// dyn smem: B stages [0, 2*STAGEB) | X region [2*STAGEB, 2*STAGEB + 2*128*HPAD*2):
//   phase A: A stages (2*STAGEB = 40960 <= 69632); phase B: H2h/H2l (69632)
#define L2U_SMEM (2 * STAGEB + 2 * 128 * HPAD * 2)   // 110592 B
__global__ void __launch_bounds__(256)
layer2u_kernel(const float* __restrict__ b2, int M) {
    extern __shared__ __nv_bfloat16 sm[];
    uint32_t sb = smem_u32(sm);
    const uint32_t XOFF = 2 * STAGEB;
    __nv_bfloat16* H2h = sm + XOFF / 2;
    __nv_bfloat16* H2l = H2h + 128 * HPAD;

    int t = threadIdx.x, lane = t & 31, wid = t >> 5;
    int wm = wid >> 1, wn = wid & 1;
    int m0 = blockIdx.x * 128;
    int rclamp = M - 1 - m0;
    int tgrp = lane >> 3, trow = lane & 7;
    int qrow = lane >> 2, qcol = (lane & 3) * 2;

    float acc[2][8][4];
#pragma unroll
    for (int i = 0; i < 2; i++)
#pragma unroll
        for (int j = 0; j < 8; j++)
#pragma unroll
            for (int k = 0; k < 4; k++) acc[i][j][k] = 0.f;

    const __nv_bfloat16* a0h = g_aggh + (size_t)m0 * HDIM;
    const __nv_bfloat16* a0l = g_aggl + (size_t)m0 * HDIM;
    const __nv_bfloat16* a1h = g_h1h + (size_t)m0 * HDIM;
    const __nv_bfloat16* a1l = g_h1l + (size_t)m0 * HDIM;

    // ---- phase A: h2 = relu([agg|h1] @ [Wl2|Wr2]^T + b2) ----
    issue_tile(sb + XOFF, sb + XOFF + TILEB, a0h, a0l, HDIM, rclamp, 0, t);
    issue_tile(sb, sb + TILEB, g_Wh + 32768, g_Wlo + 32768, 256, 127, 0, t);
    CP_COMMIT();
    for (int ch = 0; ch < 8; ch++) {
        int cur = ch & 1, nxt = (ch + 1) & 1;
        if (ch + 1 < 8) {
            int nc = ch + 1;
            const __nv_bfloat16* sh = (nc < 4) ? a0h : a1h;
            const __nv_bfloat16* sl = (nc < 4) ? a0l : a1l;
            issue_tile(sb + XOFF + nxt * STAGEB, sb + XOFF + nxt * STAGEB + TILEB,
                       sh, sl, HDIM, rclamp, (nc & 3) * 32, t);
            issue_tile(sb + nxt * STAGEB, sb + nxt * STAGEB + TILEB,
                       g_Wh + 32768, g_Wlo + 32768, 256, 127, nc * 32, t);
        }
        CP_COMMIT();
        CP_WAIT1();
        __syncthreads();
        mma_step(sm + (XOFF + cur * STAGEB) / 2, sm + (XOFF + cur * STAGEB + TILEB) / 2,
                 APAD, 0,
                 sm + (cur * STAGEB) / 2, sm + (cur * STAGEB + TILEB) / 2,
                 wm, wn, tgrp, trow, acc);
        __syncthreads();
    }
    // write h2 (bias+relu) into smem as bf16 hi/lo (overwrites phase-A A stages)
#pragma unroll
    for (int mf = 0; mf < 2; mf++)
#pragma unroll
        for (int nf = 0; nf < 8; nf++) {
            int n = wn * 64 + nf * 8 + qcol;
            float bx = __ldg(b2 + n), by = __ldg(b2 + n + 1);
#pragma unroll
            for (int half = 0; half < 2; half++) {
                int row = wm * 32 + mf * 16 + half * 8 + qrow;
                float v0 = fmaxf(acc[mf][nf][half * 2]     + bx, 0.f);
                float v1 = fmaxf(acc[mf][nf][half * 2 + 1] + by, 0.f);
                __nv_bfloat16 h0, l0, h1b, l1b;
                split_bf16(v0, h0, l0);
                split_bf16(v1, h1b, l1b);
                H2h[row * HPAD + n]     = h0;
                H2h[row * HPAD + n + 1] = h1b;
                H2l[row * HPAD + n]     = l0;
                H2l[row * HPAD + n + 1] = l1b;
            }
        }
    __syncthreads();

    // ---- phase B: U[:, y*128..] = h2 @ W3y^T, 8 B-rounds (y = r>>2) ----
    issue_tile(sb, sb + TILEB, g_Wh + 65536, g_Wlo + 65536, 128, 127, 0, t);
    CP_COMMIT();
    for (int r = 0; r < 8; r++) {
        int cur = r & 1, nxt = (r + 1) & 1;
        if ((r & 3) == 0) {
#pragma unroll
            for (int i = 0; i < 2; i++)
#pragma unroll
                for (int j = 0; j < 8; j++)
#pragma unroll
                    for (int k = 0; k < 4; k++) acc[i][j][k] = 0.f;
        }
        if (r + 1 < 8) {
            int nr = r + 1;
            issue_tile(sb + nxt * STAGEB, sb + nxt * STAGEB + TILEB,
                       g_Wh + 65536 + (nr >> 2) * 16384, g_Wlo + 65536 + (nr >> 2) * 16384,
                       128, 127, (nr & 3) * 32, t);
        }
        CP_COMMIT();
        CP_WAIT1();
        __syncthreads();
        mma_step(H2h, H2l, HPAD, (r & 3) * 32,
                 sm + (cur * STAGEB) / 2, sm + (cur * STAGEB + TILEB) / 2,
                 wm, wn, tgrp, trow, acc);
        __syncthreads();
        if ((r & 3) == 3) {
            int y = r >> 2;
#pragma unroll
            for (int mf = 0; mf < 2; mf++)
#pragma unroll
                for (int nf = 0; nf < 8; nf++) {
                    int n = wn * 64 + nf * 8 + qcol;
#pragma unroll
                    for (int half = 0; half < 2; half++) {
                        int gr = m0 + wm * 32 + mf * 16 + half * 8 + qrow;
                        if (gr < M) {
                            *(float2*)(g_U + (size_t)gr * 256 + y * 128 + n) =
                                make_float2(acc[mf][nf][half * 2], acc[mf][nf][half * 2 + 1]);
                        }
                    }
                }
        }
    }
}

// ---------------- pair head: sigmoid(W4 . relu(Ua[a]+Ub[b]+b3) + b4) ----------------
__global__ void __launch_bounds__(256)
pair_kernel(const int* __restrict__ pairs,
            const float* __restrict__ b3, const float* __restrict__ W4,
            const float* __restrict__ b4, float* __restrict__ out, int P) {
    int w    = (blockIdx.x * blockDim.x + threadIdx.x) >> 5;
    int lane = threadIdx.x & 31;
    if (w >= P) return;
    int na = __ldg(&pairs[2 * w]);
    int nb = __ldg(&pairs[2 * w + 1]);
    float4 ua = *((const float4*)(g_U + (size_t)na * 256) + lane);
    float4 ub = *((const float4*)(g_U + (size_t)nb * 256 + 128) + lane);
    float4 bv = *((const float4*)b3 + lane);
    float4 wv = *((const float4*)W4 + lane);
    float s = fmaxf(ua.x + ub.x + bv.x, 0.f) * wv.x
            + fmaxf(ua.y + ub.y + bv.y, 0.f) * wv.y
            + fmaxf(ua.z + ub.z + bv.z, 0.f) * wv.z
            + fmaxf(ua.w + ub.w + bv.w, 0.f) * wv.w;
#pragma unroll
    for (int o = 16; o > 0; o >>= 1)
        s += __shfl_xor_sync(0xffffffffu, s, o);
    if (lane == 0) out[w] = 1.0f / (1.0f + __expf(-(s + b4[0])));
}

// ---------------- launch ----------------
extern "C" void kernel_launch(void* const* d_in, const int* in_sizes, int n_in,
                              void* d_out, int out_size) {
    const float* x    = (const float*)d_in[0];
    const int*   edge = (const int*)d_in[1];
    const int*   prs  = (const int*)d_in[2];
    const float* Wl1  = (const float*)d_in[3];
    const float* Wr1  = (const float*)d_in[4];
    const float* b1   = (const float*)d_in[5];
    const float* Wl2  = (const float*)d_in[6];
    const float* Wr2  = (const float*)d_in[7];
    const float* b2   = (const float*)d_in[8];
    const float* W3   = (const float*)d_in[9];
    const float* b3   = (const float*)d_in[10];
    const float* W4   = (const float*)d_in[11];
    const float* b4   = (const float*)d_in[12];
    float* out = (float*)d_out;

    const int E = in_sizes[1] / 2;
    const int P = in_sizes[2] / 2;
    const int M = N_NODES;
    const int* src = edge;
    const int* dst = edge + E;

    float* g_h1_p;  cudaGetSymbolAddress((void**)&g_h1_p, g_h1);
    int*   g_deg_p; cudaGetSymbolAddress((void**)&g_deg_p, g_deg);

    cudaFuncSetAttribute(tgemm_kernel,   cudaFuncAttributeMaxDynamicSharedMemorySize, T1_SMEM);
    cudaFuncSetAttribute(layer2u_kernel, cudaFuncAttributeMaxDynamicSharedMemorySize, L2U_SMEM);

    // weight split + CSR build
    split_w_kernel<<<(98304 + 255) / 256, 256>>>(Wl1, Wr1, Wl2, Wr2, W3);
    cudaMemsetAsync(g_deg_p, 0, N_NODES * sizeof(int));
    count_deg_kernel<<<(E + 255) / 256, 256>>>(dst, E);
    scan_deg_kernel<<<1, 1024>>>(E);
    fill_csr_kernel<<<(E + 255) / 256, 256>>>(src, dst, E);

    const int aggBlocks = (N_NODES * 32 + 255) / 256;
    const int mTiles = (M + 127) / 128;   // 391

    // Layer 1
    agg_mean_kernel<<<aggBlocks, 256>>>(x, 0);
    tgemm_kernel<<<mTiles, 256, T1_SMEM>>>(x, b1, g_h1_p, M);
    // Layer 2 + U fused (h2 never leaves smem)
    agg_mean_kernel<<<aggBlocks, 256>>>(x, 1);
    layer2u_kernel<<<mTiles, 256, L2U_SMEM>>>(b2, M);
    // Pair head
    pair_kernel<<<(P * 32 + 255) / 256, 256>>>(prs, b3, W4, b4, out, P);
}